// round 4
// baseline (speedup 1.0000x reference)
#include <cuda_runtime.h>
#include <math.h>

#define Qn 4096
#define Nn 65536
#define Dn 32
#define D2 34      // 32 data dims + 2 folded-constant dims
#define DPAD 36    // row stride of augmented arrays (float4-friendly)
#define BM 128
#define BN 128
#define SPLITN 9
#define NT (Nn / BN)          // 512 j-tiles total
#define LOG2E 1.4426950408889634f

// scratch (no allocations allowed in kernel_launch)
__device__ float g_Xaug[Qn * DPAD];
__device__ float g_Yaug[Nn * DPAD];
__device__ float g_partial[SPLITN * Qn];
__device__ float g_logsumw;

// ---------------------------------------------------------------------------
// Prep: build augmented, log2e-scaled operands so that
//   sum_{d<34} Xaug[i][d]*Yaug[j][d] = log2e * ( x.y - 0.5||x||^2 - 0.5||y||^2 + log w_j )
// ---------------------------------------------------------------------------
__global__ void prep_x(const float* __restrict__ X) {
    int i = blockIdx.x * blockDim.x + threadIdx.x;
    if (i >= Qn) return;
    const float* xr = X + i * Dn;
    float v[Dn];
    float qn = 0.f;
#pragma unroll
    for (int d = 0; d < Dn; d++) { v[d] = xr[d]; qn += v[d] * v[d]; }
    float* o = g_Xaug + i * DPAD;
#pragma unroll
    for (int d = 0; d < Dn; d++) o[d] = v[d] * LOG2E;
    o[32] = -0.5f * LOG2E * qn;
    o[33] = 1.0f;
    o[34] = 0.f;
    o[35] = 0.f;
}

__global__ void prep_y(const float* __restrict__ Y, const float* __restrict__ W) {
    int j = blockIdx.x * blockDim.x + threadIdx.x;
    if (j >= Nn) return;
    const float* yr = Y + j * Dn;
    float v[Dn];
    float kn = 0.f;
#pragma unroll
    for (int d = 0; d < Dn; d++) { v[d] = yr[d]; kn += v[d] * v[d]; }
    float* o = g_Yaug + j * DPAD;
#pragma unroll
    for (int d = 0; d < Dn; d++) o[d] = v[d];
    o[32] = 1.0f;
    o[33] = LOG2E * (-0.5f * kn + logf(W[j]));
    o[34] = 0.f;
    o[35] = 0.f;
}

// Deterministic single-block reduction of sum(w) -> log
__global__ void sumw_kernel(const float* __restrict__ W) {
    __shared__ float red[1024];
    float s = 0.f;
    for (int j = threadIdx.x; j < Nn; j += 1024) s += W[j];
    red[threadIdx.x] = s;
    __syncthreads();
    for (int k = 512; k > 0; k >>= 1) {
        if (threadIdx.x < k) red[threadIdx.x] += red[threadIdx.x + k];
        __syncthreads();
    }
    if (threadIdx.x == 0) g_logsumw = logf(red[0]);
}

// ---------------------------------------------------------------------------
// Main: 128x128 tiles, 8x8 register blocking, fp32 FFMA + EX2 epilogue.
// Grid: (Qn/BM, SPLITN); round-robin j-tiles per split for load balance.
// ---------------------------------------------------------------------------
__global__ __launch_bounds__(256, 2) void kde_main() {
    __shared__ __align__(16) float sx[D2][BM + 4];  // +4 pad: bank-conflict-free, keeps 16B align (528B rows)
    __shared__ __align__(16) float sy[D2][BN + 4];

    const int qb = blockIdx.x * BM;
    const int split = blockIdx.y;
    const int tid = threadIdx.x;
    const int tx = tid & 15;   // j-group
    const int ty = tid >> 4;   // i-group

    // Load X tile once, transposed to [d][i] (17 float2 per row)
    for (int t = tid; t < BM * 17; t += 256) {
        int i = t / 17, dh = t % 17;
        float2 v = *(const float2*)(g_Xaug + (qb + i) * DPAD + dh * 2);
        sx[dh * 2][i] = v.x;
        sx[dh * 2 + 1][i] = v.y;
    }

    float qsum[8];
#pragma unroll
    for (int k = 0; k < 8; k++) qsum[k] = 0.f;

    for (int t = split; t < NT; t += SPLITN) {
        const int jb = t * BN;
        __syncthreads();  // also covers initial sx writes / sy reuse from prior iter
        for (int u = tid; u < BN * 17; u += 256) {
            int j = u / 17, dh = u % 17;
            float2 v = *(const float2*)(g_Yaug + (jb + j) * DPAD + dh * 2);
            sy[dh * 2][j] = v.x;
            sy[dh * 2 + 1][j] = v.y;
        }
        __syncthreads();

        float acc[8][8];
#pragma unroll
        for (int a = 0; a < 8; a++)
#pragma unroll
            for (int b = 0; b < 8; b++) acc[a][b] = 0.f;

#pragma unroll 2
        for (int d = 0; d < D2; d++) {
            float xf[8], yf[8];
#pragma unroll
            for (int k = 0; k < 8; k++) xf[k] = sx[d][ty * 8 + k];
#pragma unroll
            for (int k = 0; k < 8; k++) yf[k] = sy[d][tx * 8 + k];
#pragma unroll
            for (int a = 0; a < 8; a++)
#pragma unroll
                for (int b = 0; b < 8; b++)
                    acc[a][b] = fmaf(xf[a], yf[b], acc[a][b]);
        }

        // epilogue: acc holds log2e * s  ->  exp2 and accumulate
#pragma unroll
        for (int a = 0; a < 8; a++) {
            float s = 0.f;
#pragma unroll
            for (int b = 0; b < 8; b++) {
                float e;
                asm("ex2.approx.f32 %0, %1;" : "=f"(e) : "f"(acc[a][b]));
                s += e;
            }
            qsum[a] += s;
        }
    }

    // Deterministic in-CTA reduction across the 16 j-groups
    __syncthreads();
    float* red = (float*)sy;  // reuse as [BM][17]
#pragma unroll
    for (int k = 0; k < 8; k++) red[(ty * 8 + k) * 17 + tx] = qsum[k];
    __syncthreads();
    if (tid < BM) {
        float s = 0.f;
#pragma unroll
        for (int k = 0; k < 16; k++) s += red[tid * 17 + k];
        g_partial[split * Qn + qb + tid] = s;  // unique slot: no atomics
    }
}

__global__ void finalize(float* __restrict__ out) {
    int i = blockIdx.x * blockDim.x + threadIdx.x;
    if (i >= Qn) return;
    float s = 0.f;
#pragma unroll
    for (int k = 0; k < SPLITN; k++) s += g_partial[k * Qn + i];
    // -0.5*d*ln(2*pi) with d=32  ->  -16*ln(2pi) = -29.4060330625...
    out[i] = logf(s) - 29.40603306f - g_logsumw;
}

// ---------------------------------------------------------------------------
extern "C" void kernel_launch(void* const* d_in, const int* in_sizes, int n_in,
                              void* d_out, int out_size) {
    const float* X = (const float*)d_in[0];  // [4096,32]
    const float* Y = (const float*)d_in[1];  // [65536,32]
    const float* W = (const float*)d_in[2];  // [65536]
    float* out = (float*)d_out;

    prep_x<<<(Qn + 255) / 256, 256>>>(X);
    prep_y<<<(Nn + 255) / 256, 256>>>(Y, W);
    sumw_kernel<<<1, 1024>>>(W);
    dim3 grid(Qn / BM, SPLITN);
    kde_main<<<grid, 256>>>();
    finalize<<<(Qn + 255) / 256, 256>>>(out);
}

// round 12
// speedup vs baseline: 1.9952x; 1.9952x over previous
#include <cuda_runtime.h>
#include <cuda_fp16.h>
#include <math.h>
#include <stdint.h>

#define Qn 4096
#define Nn 65536
#define Dn 32
#define DK 48               // 32 data dims + 16-dim aug block (biases folded into GEMM)
#define BM 128
#define BN 128
#define SPLITN 9
#define NT2 512
#define LOG2E 1.4426950408889634f
#define STR 112             // smem row stride bytes (48 halves = 96B + 16B pad; conflict-free)
#define TILE_B (128 * STR)  // 14336 bytes per 128-row tile

// ---------------- device scratch ----------------
__device__ __align__(16) __half g_Xh[Qn * DK];   // hi: [0:32)=fp16(L*x), [32]=bx_h,[33]=bx_l,[34]=1,[35]=1,rest 0
__device__ __align__(16) __half g_Xl[Qn * DK];   // lo: [0:32)=residual, [32:48)=0
__device__ __align__(16) __half g_Yh[Nn * DK];   // hi: [0:32)=fp16(y), [32]=1,[33]=1,[34]=by_h,[35]=by_l,rest 0
__device__ __align__(16) __half g_Yl[Nn * DK];   // lo: [0:32)=residual, [32:48)=0
__device__ float g_partial[SPLITN * Qn];
__device__ float g_logsumw;

// ---------------- smem layout (bytes) ----------------
#define SM_XH 0                     // 14336
#define SM_XL TILE_B                // 14336
#define SM_Y  (2 * TILE_B)          // 2 bufs * (H + L) = 57344
#define SM_BYTES (6 * TILE_B)       // 86016

__device__ __forceinline__ uint32_t smem_u32(const void* p) {
    uint32_t a;
    asm("{ .reg .u64 t; cvta.to.shared.u64 t, %1; cvt.u32.u64 %0, t; }" : "=r"(a) : "l"(p));
    return a;
}

#define MMA(d, a, b0, b1) \
    asm volatile("mma.sync.aligned.m16n8k16.row.col.f32.f16.f16.f32 " \
        "{%0,%1,%2,%3}, {%4,%5,%6,%7}, {%8,%9}, {%0,%1,%2,%3};" \
        : "+f"((d)[0]), "+f"((d)[1]), "+f"((d)[2]), "+f"((d)[3]) \
        : "r"((a)[0]), "r"((a)[1]), "r"((a)[2]), "r"((a)[3]), "r"(b0), "r"(b1))

#define CPA16(dst, src) \
    asm volatile("cp.async.cg.shared.global [%0], [%1], 16;" :: "r"(dst), "l"(src) : "memory")

// ---------------- prep: build 48-wide augmented hi/lo rows ----------------
__global__ void prep_x48(const float* __restrict__ X) {
    int i = blockIdx.x * blockDim.x + threadIdx.x;
    if (i >= Qn) return;
    __half h[DK], l[DK];
    float qn = 0.f;
#pragma unroll
    for (int d = 0; d < Dn; d++) {
        float x = X[i * Dn + d];
        qn += x * x;
        float xs = x * LOG2E;
        __half hh = __float2half_rn(xs);
        h[d] = hh;
        l[d] = __float2half_rn(xs - __half2float(hh));
    }
    float bxv = -0.5f * LOG2E * qn;
    __half bh = __float2half_rn(bxv);
    __half bl = __float2half_rn(bxv - __half2float(bh));
    h[32] = bh; h[33] = bl;
    h[34] = __float2half_rn(1.0f); h[35] = __float2half_rn(1.0f);
#pragma unroll
    for (int d = 36; d < DK; d++) h[d] = __float2half_rn(0.f);
#pragma unroll
    for (int d = 32; d < DK; d++) l[d] = __float2half_rn(0.f);
#pragma unroll
    for (int c = 0; c < 6; c++) {
        *(uint4*)(g_Xh + i * DK + c * 8) = *(const uint4*)(h + c * 8);
        *(uint4*)(g_Xl + i * DK + c * 8) = *(const uint4*)(l + c * 8);
    }
}

__global__ void prep_y48(const float* __restrict__ Y, const float* __restrict__ W) {
    int j = blockIdx.x * blockDim.x + threadIdx.x;
    if (j >= Nn) return;
    __half h[DK], l[DK];
    float kn = 0.f;
#pragma unroll
    for (int d = 0; d < Dn; d++) {
        float y = Y[j * Dn + d];
        kn += y * y;
        __half hh = __float2half_rn(y);
        h[d] = hh;
        l[d] = __float2half_rn(y - __half2float(hh));
    }
    float byv = LOG2E * (-0.5f * kn + logf(W[j]));
    __half bh = __float2half_rn(byv);
    __half bl = __float2half_rn(byv - __half2float(bh));
    h[32] = __float2half_rn(1.0f); h[33] = __float2half_rn(1.0f);
    h[34] = bh; h[35] = bl;
#pragma unroll
    for (int d = 36; d < DK; d++) h[d] = __float2half_rn(0.f);
#pragma unroll
    for (int d = 32; d < DK; d++) l[d] = __float2half_rn(0.f);
#pragma unroll
    for (int c = 0; c < 6; c++) {
        *(uint4*)(g_Yh + j * DK + c * 8) = *(const uint4*)(h + c * 8);
        *(uint4*)(g_Yl + j * DK + c * 8) = *(const uint4*)(l + c * 8);
    }
}

__global__ void sumw_kernel(const float* __restrict__ W) {
    __shared__ float red[1024];
    float s = 0.f;
    for (int j = threadIdx.x; j < Nn / 4; j += 1024) {
        float4 v = ((const float4*)W)[j];
        s += (v.x + v.y) + (v.z + v.w);
    }
    red[threadIdx.x] = s;
    __syncthreads();
    for (int k = 512; k > 0; k >>= 1) {
        if (threadIdx.x < k) red[threadIdx.x] += red[threadIdx.x + k];
        __syncthreads();
    }
    if (threadIdx.x == 0) g_logsumw = logf(red[0]);
}

// ---------------- main ----------------
__device__ __forceinline__ void prefetch_tile(uint32_t sb, int buf, int jb, int tid) {
    int arr = tid >> 7, row = tid & 127;
    const __half* src = (arr ? g_Yl : g_Yh) + (jb + row) * DK;
    uint32_t dst0 = sb + SM_Y + buf * (2 * TILE_B) + arr * TILE_B + row * STR;
#pragma unroll
    for (int c = 0; c < 6; c++)
        CPA16(dst0 + c * 16, src + c * 8);
}

__global__ __launch_bounds__(256, 2) void kde_main() {
    extern __shared__ __align__(128) char smem[];
    const uint32_t sb = smem_u32(smem);
    const int tid = threadIdx.x, lane = tid & 31, wid = tid >> 5;
    const int wm = wid >> 1, wn = wid & 1;    // 4 warps M-dir, 2 warps N-dir
    const int qrow = lane >> 2;               // PTX groupID
    const int kb = (lane & 3) * 4;            // k-pair byte offset
    const int qb = blockIdx.x * BM;
    const int split = blockIdx.y;

    prefetch_tile(sb, 0, split * BN, tid);
    asm volatile("cp.async.commit_group;" ::: "memory");

    // load X tiles (hi, lo) into padded smem
    {
        int arr = tid >> 7, row = tid & 127;
        const __half* src = (arr ? g_Xl : g_Xh) + (qb + row) * DK;
        char* dst = smem + (arr ? SM_XL : SM_XH) + row * STR;
#pragma unroll
        for (int c = 0; c < 6; c++)
            *(uint4*)(dst + c * 16) = *(const uint4*)(src + c * 8);
    }
    __syncthreads();

    // hoist A fragments (PTX m16n8k16 A table):
    //   a0=(r,k) a1=(r+8,k) a2=(r,k+8) a3=(r+8,k+8)
    uint32_t ah[2][2][4], al[2][2][4], aga[2][4];
#pragma unroll
    for (int mt = 0; mt < 2; mt++) {
        int row = wm * 32 + mt * 16 + qrow;
#pragma unroll
        for (int kk = 0; kk < 2; kk++) {
            const char* ph = smem + SM_XH + row * STR + kk * 32 + kb;
            const char* pl = smem + SM_XL + row * STR + kk * 32 + kb;
            ah[mt][kk][0] = *(const uint32_t*)(ph);
            ah[mt][kk][1] = *(const uint32_t*)(ph + 8 * STR);
            ah[mt][kk][2] = *(const uint32_t*)(ph + 16);
            ah[mt][kk][3] = *(const uint32_t*)(ph + 8 * STR + 16);
            al[mt][kk][0] = *(const uint32_t*)(pl);
            al[mt][kk][1] = *(const uint32_t*)(pl + 8 * STR);
            al[mt][kk][2] = *(const uint32_t*)(pl + 16);
            al[mt][kk][3] = *(const uint32_t*)(pl + 8 * STR + 16);
        }
        const char* pa = smem + SM_XH + row * STR + 64 + kb;   // aug block k=32..47
        aga[mt][0] = *(const uint32_t*)(pa);
        aga[mt][1] = *(const uint32_t*)(pa + 8 * STR);
        aga[mt][2] = *(const uint32_t*)(pa + 16);
        aga[mt][3] = *(const uint32_t*)(pa + 8 * STR + 16);
    }

    float rs[4] = {0.f, 0.f, 0.f, 0.f};
    int idx = 0;
    for (int t = split; t < NT2; t += SPLITN, idx++) {
        const int buf = idx & 1;
        const int tn = t + SPLITN;
        if (tn < NT2) {
            prefetch_tile(sb, buf ^ 1, tn * BN, tid);
            asm volatile("cp.async.commit_group;" ::: "memory");
            asm volatile("cp.async.wait_group 1;" ::: "memory");
        } else {
            asm volatile("cp.async.wait_group 0;" ::: "memory");
        }
        __syncthreads();

        const char* yb = smem + SM_Y + buf * (2 * TILE_B);

#pragma unroll
        for (int g = 0; g < 4; g++) {
            // B fragments (PTX table): b0=(k=(lane%4)*2, n=qrow), b1=k+8
            uint32_t bh[2][2][2], bl[2][2][2], bga[2][2];
#pragma unroll
            for (int nt = 0; nt < 2; nt++) {
                int nrow = wn * 64 + g * 16 + nt * 8 + qrow;
#pragma unroll
                for (int kk = 0; kk < 2; kk++) {
                    const char* p = yb + nrow * STR + kk * 32 + kb;
                    bh[kk][nt][0] = *(const uint32_t*)(p);
                    bh[kk][nt][1] = *(const uint32_t*)(p + 16);
                    bl[kk][nt][0] = *(const uint32_t*)(p + TILE_B);
                    bl[kk][nt][1] = *(const uint32_t*)(p + TILE_B + 16);
                }
                const char* pa = yb + nrow * STR + 64 + kb;
                bga[nt][0] = *(const uint32_t*)(pa);
                bga[nt][1] = *(const uint32_t*)(pa + 16);
            }

            float acc[2][2][4];
#pragma unroll
            for (int mt = 0; mt < 2; mt++)
#pragma unroll
                for (int nt = 0; nt < 2; nt++)
#pragma unroll
                    for (int q = 0; q < 4; q++) acc[mt][nt][q] = 0.f;

#pragma unroll
            for (int kk = 0; kk < 2; kk++)
#pragma unroll
                for (int mt = 0; mt < 2; mt++)
#pragma unroll
                    for (int nt = 0; nt < 2; nt++) {
                        MMA(acc[mt][nt], ah[mt][kk], bh[kk][nt][0], bh[kk][nt][1]);
                        MMA(acc[mt][nt], al[mt][kk], bh[kk][nt][0], bh[kk][nt][1]);
                        MMA(acc[mt][nt], ah[mt][kk], bl[kk][nt][0], bl[kk][nt][1]);
                    }
#pragma unroll
            for (int mt = 0; mt < 2; mt++)
#pragma unroll
                for (int nt = 0; nt < 2; nt++)
                    MMA(acc[mt][nt], aga[mt], bga[nt][0], bga[nt][1]);

            // epilogue: acc IS the full exp2 argument — no per-column bias needed
#pragma unroll
            for (int mt = 0; mt < 2; mt++)
#pragma unroll
                for (int nt = 0; nt < 2; nt++) {
                    float e0, e1, e2, e3;
                    asm("ex2.approx.f32 %0, %1;" : "=f"(e0) : "f"(acc[mt][nt][0]));
                    asm("ex2.approx.f32 %0, %1;" : "=f"(e1) : "f"(acc[mt][nt][1]));
                    asm("ex2.approx.f32 %0, %1;" : "=f"(e2) : "f"(acc[mt][nt][2]));
                    asm("ex2.approx.f32 %0, %1;" : "=f"(e3) : "f"(acc[mt][nt][3]));
                    rs[mt * 2 + 0] += e0 + e1;
                    rs[mt * 2 + 1] += e2 + e3;
                }
        }
        __syncthreads();   // all warps done with buf before refill
    }

    // deterministic reduction: 4 lanes share each row
#pragma unroll
    for (int k = 0; k < 4; k++) {
        rs[k] += __shfl_xor_sync(0xffffffffu, rs[k], 1);
        rs[k] += __shfl_xor_sync(0xffffffffu, rs[k], 2);
    }
    __syncthreads();
    float* red = (float*)(smem + SM_Y);  // 256 floats
    if ((lane & 3) == 0) {
#pragma unroll
        for (int k = 0; k < 4; k++) {
            int mt = k >> 1, hf = k & 1;
            int row = wm * 32 + mt * 16 + (lane >> 2) + hf * 8;
            red[wn * 128 + row] = rs[k];
        }
    }
    __syncthreads();
    if (tid < 128)
        g_partial[split * Qn + qb + tid] = red[tid] + red[128 + tid];
}

__global__ void finalize(float* __restrict__ out) {
    int i = blockIdx.x * blockDim.x + threadIdx.x;
    if (i >= Qn) return;
    float s = 0.f;
#pragma unroll
    for (int k = 0; k < SPLITN; k++) s += g_partial[k * Qn + i];
    // ln(sum) - 16*ln(2pi) - ln(sum w)   (all row/col biases already inside the GEMM)
    out[i] = logf(s) - 29.40603306f - g_logsumw;
}

// ---------------------------------------------------------------------------
extern "C" void kernel_launch(void* const* d_in, const int* in_sizes, int n_in,
                              void* d_out, int out_size) {
    const float* X = (const float*)d_in[0];  // [4096,32]
    const float* Y = (const float*)d_in[1];  // [65536,32]
    const float* W = (const float*)d_in[2];  // [65536]
    float* out = (float*)d_out;

    cudaFuncSetAttribute(kde_main, cudaFuncAttributeMaxDynamicSharedMemorySize, SM_BYTES);

    prep_x48<<<(Qn + 127) / 128, 128>>>(X);
    prep_y48<<<(Nn + 127) / 128, 128>>>(Y, W);
    sumw_kernel<<<1, 1024>>>(W);
    dim3 grid(Qn / BM, SPLITN);
    kde_main<<<grid, 256, SM_BYTES>>>();
    finalize<<<(Qn + 255) / 256, 256>>>(out);
}

// round 13
// speedup vs baseline: 3.6502x; 1.8295x over previous
#include <cuda_runtime.h>
#include <cuda_fp16.h>
#include <math.h>
#include <stdint.h>

#define Qn 4096
#define Nn 65536
#define Dn 32
#define DK 48               // 32 data dims + 16-dim aug block (biases folded into GEMM)
#define BM 128
#define BN 128
#define SPLITN 9
#define NT2 512
#define LOG2E 1.4426950408889634f
#define STR 112             // smem row stride bytes (48 halves = 96B + 16B pad)
#define TILE_B (128 * STR)  // 14336 bytes per 128-row tile

// ---------------- device scratch ----------------
__device__ __align__(16) __half g_Xh[Qn * DK];   // hi: [0:32)=fp16(L*x), [32]=bx_h,[33]=bx_l,[34]=1,[35]=1,rest 0
__device__ __align__(16) __half g_Xl[Qn * DK];   // lo: [0:32)=residual, [32:48)=0
__device__ __align__(16) __half g_Yh[Nn * DK];   // [0:32)=fp16(y), [32]=1,[33]=1,[34]=by_h,[35]=by_l,rest 0
__device__ float g_partial[SPLITN * Qn];
__device__ float g_wpart[Nn / 256];
__device__ float g_logsumw;

// ---------------- smem layout (bytes) ----------------
#define SM_XH 0                     // 14336
#define SM_XL TILE_B                // 14336
#define SM_Y  (2 * TILE_B)          // 4 bufs * 14336 = 57344
#define SM_BYTES (6 * TILE_B)       // 86016

__device__ __forceinline__ uint32_t smem_u32(const void* p) {
    uint32_t a;
    asm("{ .reg .u64 t; cvta.to.shared.u64 t, %1; cvt.u32.u64 %0, t; }" : "=r"(a) : "l"(p));
    return a;
}

#define MMA(d, a, b0, b1) \
    asm volatile("mma.sync.aligned.m16n8k16.row.col.f32.f16.f16.f32 " \
        "{%0,%1,%2,%3}, {%4,%5,%6,%7}, {%8,%9}, {%0,%1,%2,%3};" \
        : "+f"((d)[0]), "+f"((d)[1]), "+f"((d)[2]), "+f"((d)[3]) \
        : "r"((a)[0]), "r"((a)[1]), "r"((a)[2]), "r"((a)[3]), "r"(b0), "r"(b1))

#define CPA16(dst, src) \
    asm volatile("cp.async.cg.shared.global [%0], [%1], 16;" :: "r"(dst), "l"(src) : "memory")

// ---------------- prep ----------------
__global__ void prep_x48(const float* __restrict__ X) {
    int i = blockIdx.x * blockDim.x + threadIdx.x;
    if (i >= Qn) return;
    __half h[DK], l[DK];
    float qn = 0.f;
#pragma unroll
    for (int d = 0; d < Dn; d++) {
        float x = X[i * Dn + d];
        qn += x * x;
        float xs = x * LOG2E;
        __half hh = __float2half_rn(xs);
        h[d] = hh;
        l[d] = __float2half_rn(xs - __half2float(hh));
    }
    float bxv = -0.5f * LOG2E * qn;
    __half bh = __float2half_rn(bxv);
    __half bl = __float2half_rn(bxv - __half2float(bh));
    h[32] = bh; h[33] = bl;
    h[34] = __float2half_rn(1.0f); h[35] = __float2half_rn(1.0f);
#pragma unroll
    for (int d = 36; d < DK; d++) h[d] = __float2half_rn(0.f);
#pragma unroll
    for (int d = 32; d < DK; d++) l[d] = __float2half_rn(0.f);
#pragma unroll
    for (int c = 0; c < 6; c++) {
        *(uint4*)(g_Xh + i * DK + c * 8) = *(const uint4*)(h + c * 8);
        *(uint4*)(g_Xl + i * DK + c * 8) = *(const uint4*)(l + c * 8);
    }
}

// also produces per-block w partial sums (deterministic in-block tree)
__global__ void prep_y48(const float* __restrict__ Y, const float* __restrict__ W) {
    __shared__ float red[256];
    int j = blockIdx.x * blockDim.x + threadIdx.x;
    __half h[DK];
    float kn = 0.f;
#pragma unroll
    for (int d = 0; d < Dn; d++) {
        float y = Y[j * Dn + d];
        kn += y * y;
        h[d] = __float2half_rn(y);
    }
    float w = W[j];
    float byv = LOG2E * (-0.5f * kn + logf(w));
    __half bh = __float2half_rn(byv);
    __half bl = __float2half_rn(byv - __half2float(bh));
    h[32] = __float2half_rn(1.0f); h[33] = __float2half_rn(1.0f);
    h[34] = bh; h[35] = bl;
#pragma unroll
    for (int d = 36; d < DK; d++) h[d] = __float2half_rn(0.f);
#pragma unroll
    for (int c = 0; c < 6; c++)
        *(uint4*)(g_Yh + j * DK + c * 8) = *(const uint4*)(h + c * 8);

    red[threadIdx.x] = w;
    __syncthreads();
    for (int k = 128; k > 0; k >>= 1) {
        if (threadIdx.x < k) red[threadIdx.x] += red[threadIdx.x + k];
        __syncthreads();
    }
    if (threadIdx.x == 0) g_wpart[blockIdx.x] = red[0];
}

__global__ void sumw2() {
    __shared__ float red[256];
    red[threadIdx.x] = g_wpart[threadIdx.x];
    __syncthreads();
    for (int k = 128; k > 0; k >>= 1) {
        if (threadIdx.x < k) red[threadIdx.x] += red[threadIdx.x + k];
        __syncthreads();
    }
    if (threadIdx.x == 0) g_logsumw = logf(red[0]);
}

// ---------------- main ----------------
__device__ __forceinline__ void prefetch_tile(uint32_t sb, int buf, int jb, int tid) {
    // 128 rows * 6 chunks of 16B = 768 chunks, 3 per thread
    uint32_t base = sb + SM_Y + buf * TILE_B;
#pragma unroll
    for (int c = 0; c < 3; c++) {
        int id = tid + 256 * c;
        int row = id / 6, col = id % 6;
        CPA16(base + row * STR + col * 16, g_Yh + (jb + row) * DK + col * 8);
    }
}

__global__ __launch_bounds__(256, 2) void kde_main() {
    extern __shared__ __align__(128) char smem[];
    const uint32_t sb = smem_u32(smem);
    const int tid = threadIdx.x, lane = tid & 31, wid = tid >> 5;
    const int wm = wid >> 1, wn = wid & 1;    // 4 warps M-dir, 2 warps N-dir
    const int qrow = lane >> 2;               // PTX groupID
    const int kb = (lane & 3) * 4;            // k-pair byte offset
    const int qb = blockIdx.x * BM;
    const int split = blockIdx.y;

    // prologue: 2 tiles in flight before touching X
    prefetch_tile(sb, 0, split * BN, tid);
    asm volatile("cp.async.commit_group;" ::: "memory");
    prefetch_tile(sb, 1, (split + SPLITN) * BN, tid);
    asm volatile("cp.async.commit_group;" ::: "memory");

    // load X tiles (hi, lo) into padded smem
    {
        int arr = tid >> 7, row = tid & 127;
        const __half* src = (arr ? g_Xl : g_Xh) + (qb + row) * DK;
        char* dst = smem + (arr ? SM_XL : SM_XH) + row * STR;
#pragma unroll
        for (int c = 0; c < 6; c++)
            *(uint4*)(dst + c * 16) = *(const uint4*)(src + c * 8);
    }
    __syncthreads();

    // hoist A fragments (validated m16n8k16 A table):
    //   a0=(r,k) a1=(r+8,k) a2=(r,k+8) a3=(r+8,k+8)
    uint32_t ah[2][2][4], al[2][2][4], aga[2][4];
#pragma unroll
    for (int mt = 0; mt < 2; mt++) {
        int row = wm * 32 + mt * 16 + qrow;
#pragma unroll
        for (int kk = 0; kk < 2; kk++) {
            const char* ph = smem + SM_XH + row * STR + kk * 32 + kb;
            const char* pl = smem + SM_XL + row * STR + kk * 32 + kb;
            ah[mt][kk][0] = *(const uint32_t*)(ph);
            ah[mt][kk][1] = *(const uint32_t*)(ph + 8 * STR);
            ah[mt][kk][2] = *(const uint32_t*)(ph + 16);
            ah[mt][kk][3] = *(const uint32_t*)(ph + 8 * STR + 16);
            al[mt][kk][0] = *(const uint32_t*)(pl);
            al[mt][kk][1] = *(const uint32_t*)(pl + 8 * STR);
            al[mt][kk][2] = *(const uint32_t*)(pl + 16);
            al[mt][kk][3] = *(const uint32_t*)(pl + 8 * STR + 16);
        }
        const char* pa = smem + SM_XH + row * STR + 64 + kb;   // aug block k=32..47
        aga[mt][0] = *(const uint32_t*)(pa);
        aga[mt][1] = *(const uint32_t*)(pa + 8 * STR);
        aga[mt][2] = *(const uint32_t*)(pa + 16);
        aga[mt][3] = *(const uint32_t*)(pa + 8 * STR + 16);
    }

    float rs[4] = {0.f, 0.f, 0.f, 0.f};
    int idx = 0;
    for (int t = split; t < NT2; t += SPLITN, idx++) {
        const int buf = idx & 3;
        const int tn2 = t + 2 * SPLITN;
        if (tn2 < NT2)
            prefetch_tile(sb, (idx + 2) & 3, tn2 * BN, tid);
        asm volatile("cp.async.commit_group;" ::: "memory");   // possibly empty group
        asm volatile("cp.async.wait_group 2;" ::: "memory");   // tile idx resident
        __syncthreads();

        const char* yb = smem + SM_Y + buf * TILE_B;

#pragma unroll
        for (int g = 0; g < 4; g++) {
            // B fragments (hi only): b0=(k=(lane%4)*2, n=qrow), b1=k+8
            uint32_t bh[2][2][2], bga[2][2];   // [kk][nt][reg]
#pragma unroll
            for (int nt = 0; nt < 2; nt++) {
                int nrow = wn * 64 + g * 16 + nt * 8 + qrow;
#pragma unroll
                for (int kk = 0; kk < 2; kk++) {
                    const char* p = yb + nrow * STR + kk * 32 + kb;
                    bh[kk][nt][0] = *(const uint32_t*)(p);
                    bh[kk][nt][1] = *(const uint32_t*)(p + 16);
                }
                const char* pa = yb + nrow * STR + 64 + kb;
                bga[nt][0] = *(const uint32_t*)(pa);
                bga[nt][1] = *(const uint32_t*)(pa + 16);
            }

            float acc[2][2][4];
#pragma unroll
            for (int mt = 0; mt < 2; mt++)
#pragma unroll
                for (int nt = 0; nt < 2; nt++)
#pragma unroll
                    for (int q = 0; q < 4; q++) acc[mt][nt][q] = 0.f;

#pragma unroll
            for (int kk = 0; kk < 2; kk++)
#pragma unroll
                for (int mt = 0; mt < 2; mt++)
#pragma unroll
                    for (int nt = 0; nt < 2; nt++) {
                        MMA(acc[mt][nt], ah[mt][kk], bh[kk][nt][0], bh[kk][nt][1]);
                        MMA(acc[mt][nt], al[mt][kk], bh[kk][nt][0], bh[kk][nt][1]);
                    }
#pragma unroll
            for (int mt = 0; mt < 2; mt++)
#pragma unroll
                for (int nt = 0; nt < 2; nt++)
                    MMA(acc[mt][nt], aga[mt], bga[nt][0], bga[nt][1]);

            // epilogue: acc IS the full exp2 argument
#pragma unroll
            for (int mt = 0; mt < 2; mt++)
#pragma unroll
                for (int nt = 0; nt < 2; nt++) {
                    float e0, e1, e2, e3;
                    asm("ex2.approx.f32 %0, %1;" : "=f"(e0) : "f"(acc[mt][nt][0]));
                    asm("ex2.approx.f32 %0, %1;" : "=f"(e1) : "f"(acc[mt][nt][1]));
                    asm("ex2.approx.f32 %0, %1;" : "=f"(e2) : "f"(acc[mt][nt][2]));
                    asm("ex2.approx.f32 %0, %1;" : "=f"(e3) : "f"(acc[mt][nt][3]));
                    rs[mt * 2 + 0] += e0 + e1;
                    rs[mt * 2 + 1] += e2 + e3;
                }
        }
    }

    // deterministic reduction: 4 lanes share each row
#pragma unroll
    for (int k = 0; k < 4; k++) {
        rs[k] += __shfl_xor_sync(0xffffffffu, rs[k], 1);
        rs[k] += __shfl_xor_sync(0xffffffffu, rs[k], 2);
    }
    __syncthreads();
    float* red = (float*)(smem + SM_Y);  // 256 floats, buffers no longer needed
    if ((lane & 3) == 0) {
#pragma unroll
        for (int k = 0; k < 4; k++) {
            int mt = k >> 1, hf = k & 1;
            int row = wm * 32 + mt * 16 + (lane >> 2) + hf * 8;
            red[wn * 128 + row] = rs[k];
        }
    }
    __syncthreads();
    if (tid < 128)
        g_partial[split * Qn + qb + tid] = red[tid] + red[128 + tid];
}

__global__ void finalize(float* __restrict__ out) {
    int i = blockIdx.x * blockDim.x + threadIdx.x;
    if (i >= Qn) return;
    float s = 0.f;
#pragma unroll
    for (int k = 0; k < SPLITN; k++) s += g_partial[k * Qn + i];
    out[i] = logf(s) - 29.40603306f - g_logsumw;
}

// ---------------------------------------------------------------------------
extern "C" void kernel_launch(void* const* d_in, const int* in_sizes, int n_in,
                              void* d_out, int out_size) {
    const float* X = (const float*)d_in[0];  // [4096,32]
    const float* Y = (const float*)d_in[1];  // [65536,32]
    const float* W = (const float*)d_in[2];  // [65536]
    float* out = (float*)d_out;

    cudaFuncSetAttribute(kde_main, cudaFuncAttributeMaxDynamicSharedMemorySize, SM_BYTES);

    prep_x48<<<(Qn + 255) / 256, 256>>>(X);
    prep_y48<<<Nn / 256, 256>>>(Y, W);
    sumw2<<<1, 256>>>();
    dim3 grid(Qn / BM, SPLITN);
    kde_main<<<grid, 256, SM_BYTES>>>();
    finalize<<<(Qn + 255) / 256, 256>>>(out);
}

// round 14
// speedup vs baseline: 4.6262x; 1.2674x over previous
#include <cuda_runtime.h>
#include <cuda_fp16.h>
#include <math.h>
#include <stdint.h>

#define Qn 4096
#define Nn 65536
#define Dn 32
#define DK 48               // 32 data dims + 16-dim aug block (biases folded into GEMM)
#define BM 128
#define BN 128
#define SPLITN 9
#define NT2 512
#define LOG2E 1.4426950408889634f
#define STR 112             // smem row stride bytes (48 halves = 96B + 16B pad)
#define TILE_B (128 * STR)  // 14336 bytes per 128-row tile

// ---------------- device scratch ----------------
__device__ __align__(16) __half g_Xh[Qn * DK];   // [0:32)=fp16(L*x), [32]=bx_h,[33]=bx_l,[34]=1,[35]=1,rest 0
__device__ __align__(16) __half g_Yh[Nn * DK];   // [0:32)=fp16(y), [32]=1,[33]=1,[34]=by_h,[35]=by_l,rest 0
__device__ float g_partial[SPLITN * Qn];
__device__ float g_wpart[Nn / 256];
__device__ float g_logsumw;

// ---------------- smem layout (bytes) ----------------
#define SM_XH 0                     // 14336
#define SM_Y  TILE_B                // 4 bufs * 14336 = 57344
#define SM_BYTES (5 * TILE_B)       // 71680

__device__ __forceinline__ uint32_t smem_u32(const void* p) {
    uint32_t a;
    asm("{ .reg .u64 t; cvta.to.shared.u64 t, %1; cvt.u32.u64 %0, t; }" : "=r"(a) : "l"(p));
    return a;
}

#define MMA(d, a, b0, b1) \
    asm volatile("mma.sync.aligned.m16n8k16.row.col.f32.f16.f16.f32 " \
        "{%0,%1,%2,%3}, {%4,%5,%6,%7}, {%8,%9}, {%0,%1,%2,%3};" \
        : "+f"((d)[0]), "+f"((d)[1]), "+f"((d)[2]), "+f"((d)[3]) \
        : "r"((a)[0]), "r"((a)[1]), "r"((a)[2]), "r"((a)[3]), "r"(b0), "r"(b1))

#define CPA16(dst, src) \
    asm volatile("cp.async.cg.shared.global [%0], [%1], 16;" :: "r"(dst), "l"(src) : "memory")

// ---------------- prep ----------------
__global__ void prep_x48(const float* __restrict__ X) {
    int i = blockIdx.x * blockDim.x + threadIdx.x;
    if (i >= Qn) return;
    __half h[DK];
    float qn = 0.f;
#pragma unroll
    for (int d = 0; d < Dn; d++) {
        float x = X[i * Dn + d];
        qn += x * x;
        h[d] = __float2half_rn(x * LOG2E);
    }
    float bxv = -0.5f * LOG2E * qn;
    __half bh = __float2half_rn(bxv);
    __half bl = __float2half_rn(bxv - __half2float(bh));
    h[32] = bh; h[33] = bl;
    h[34] = __float2half_rn(1.0f); h[35] = __float2half_rn(1.0f);
#pragma unroll
    for (int d = 36; d < DK; d++) h[d] = __float2half_rn(0.f);
#pragma unroll
    for (int c = 0; c < 6; c++)
        *(uint4*)(g_Xh + i * DK + c * 8) = *(const uint4*)(h + c * 8);
}

// also produces per-block w partial sums (deterministic in-block tree)
__global__ void prep_y48(const float* __restrict__ Y, const float* __restrict__ W) {
    __shared__ float red[256];
    int j = blockIdx.x * blockDim.x + threadIdx.x;
    __half h[DK];
    float kn = 0.f;
#pragma unroll
    for (int d = 0; d < Dn; d++) {
        float y = Y[j * Dn + d];
        kn += y * y;
        h[d] = __float2half_rn(y);
    }
    float w = W[j];
    float byv = LOG2E * (-0.5f * kn + logf(w));
    __half bh = __float2half_rn(byv);
    __half bl = __float2half_rn(byv - __half2float(bh));
    h[32] = __float2half_rn(1.0f); h[33] = __float2half_rn(1.0f);
    h[34] = bh; h[35] = bl;
#pragma unroll
    for (int d = 36; d < DK; d++) h[d] = __float2half_rn(0.f);
#pragma unroll
    for (int c = 0; c < 6; c++)
        *(uint4*)(g_Yh + j * DK + c * 8) = *(const uint4*)(h + c * 8);

    red[threadIdx.x] = w;
    __syncthreads();
    for (int k = 128; k > 0; k >>= 1) {
        if (threadIdx.x < k) red[threadIdx.x] += red[threadIdx.x + k];
        __syncthreads();
    }
    if (threadIdx.x == 0) g_wpart[blockIdx.x] = red[0];
}

__global__ void sumw2() {
    __shared__ float red[256];
    red[threadIdx.x] = g_wpart[threadIdx.x];
    __syncthreads();
    for (int k = 128; k > 0; k >>= 1) {
        if (threadIdx.x < k) red[threadIdx.x] += red[threadIdx.x + k];
        __syncthreads();
    }
    if (threadIdx.x == 0) g_logsumw = logf(red[0]);
}

// ---------------- main ----------------
__device__ __forceinline__ void prefetch_tile(uint32_t sb, int buf, int jb, int tid) {
    // 128 rows * 6 chunks of 16B = 768 chunks, 3 per thread
    uint32_t base = sb + SM_Y + buf * TILE_B;
#pragma unroll
    for (int c = 0; c < 3; c++) {
        int id = tid + 256 * c;
        int row = id / 6, col = id % 6;
        CPA16(base + row * STR + col * 16, g_Yh + (jb + row) * DK + col * 8);
    }
}

__global__ __launch_bounds__(256, 2) void kde_main() {
    extern __shared__ __align__(128) char smem[];
    const uint32_t sb = smem_u32(smem);
    const int tid = threadIdx.x, lane = tid & 31, wid = tid >> 5;
    const int wm = wid >> 1, wn = wid & 1;    // 4 warps M-dir, 2 warps N-dir
    const int qrow = lane >> 2;               // PTX groupID
    const int kb = (lane & 3) * 4;            // k-pair byte offset
    const int qb = blockIdx.x * BM;
    const int split = blockIdx.y;

    // prologue: 2 tiles in flight before touching X
    prefetch_tile(sb, 0, split * BN, tid);
    asm volatile("cp.async.commit_group;" ::: "memory");
    prefetch_tile(sb, 1, (split + SPLITN) * BN, tid);
    asm volatile("cp.async.commit_group;" ::: "memory");

    // load X tile into padded smem (128 rows * 6 chunks, 3 per thread)
#pragma unroll
    for (int c = 0; c < 3; c++) {
        int id = tid + 256 * c;
        int row = id / 6, col = id % 6;
        *(uint4*)(smem + SM_XH + row * STR + col * 16) =
            *(const uint4*)(g_Xh + (qb + row) * DK + col * 8);
    }
    __syncthreads();

    // hoist A fragments (validated m16n8k16 A table):
    //   a0=(r,k) a1=(r+8,k) a2=(r,k+8) a3=(r+8,k+8)
    uint32_t ah[2][2][4], aga[2][4];
#pragma unroll
    for (int mt = 0; mt < 2; mt++) {
        int row = wm * 32 + mt * 16 + qrow;
#pragma unroll
        for (int kk = 0; kk < 2; kk++) {
            const char* ph = smem + SM_XH + row * STR + kk * 32 + kb;
            ah[mt][kk][0] = *(const uint32_t*)(ph);
            ah[mt][kk][1] = *(const uint32_t*)(ph + 8 * STR);
            ah[mt][kk][2] = *(const uint32_t*)(ph + 16);
            ah[mt][kk][3] = *(const uint32_t*)(ph + 8 * STR + 16);
        }
        const char* pa = smem + SM_XH + row * STR + 64 + kb;   // aug block k=32..47
        aga[mt][0] = *(const uint32_t*)(pa);
        aga[mt][1] = *(const uint32_t*)(pa + 8 * STR);
        aga[mt][2] = *(const uint32_t*)(pa + 16);
        aga[mt][3] = *(const uint32_t*)(pa + 8 * STR + 16);
    }

    float rs[4] = {0.f, 0.f, 0.f, 0.f};
    int idx = 0;
    for (int t = split; t < NT2; t += SPLITN, idx++) {
        const int buf = idx & 3;
        const int tn2 = t + 2 * SPLITN;
        if (tn2 < NT2)
            prefetch_tile(sb, (idx + 2) & 3, tn2 * BN, tid);
        asm volatile("cp.async.commit_group;" ::: "memory");   // possibly empty group
        asm volatile("cp.async.wait_group 2;" ::: "memory");   // tile idx resident
        __syncthreads();

        const char* yb = smem + SM_Y + buf * TILE_B;

#pragma unroll
        for (int g = 0; g < 4; g++) {
            // B fragments: b0=(k=(lane%4)*2, n=qrow), b1=k+8
            uint32_t bh[2][2][2], bga[2][2];   // [kk][nt][reg]
#pragma unroll
            for (int nt = 0; nt < 2; nt++) {
                int nrow = wn * 64 + g * 16 + nt * 8 + qrow;
#pragma unroll
                for (int kk = 0; kk < 2; kk++) {
                    const char* p = yb + nrow * STR + kk * 32 + kb;
                    bh[kk][nt][0] = *(const uint32_t*)(p);
                    bh[kk][nt][1] = *(const uint32_t*)(p + 16);
                }
                const char* pa = yb + nrow * STR + 64 + kb;
                bga[nt][0] = *(const uint32_t*)(pa);
                bga[nt][1] = *(const uint32_t*)(pa + 16);
            }

            float acc[2][2][4];
#pragma unroll
            for (int mt = 0; mt < 2; mt++)
#pragma unroll
                for (int nt = 0; nt < 2; nt++)
#pragma unroll
                    for (int q = 0; q < 4; q++) acc[mt][nt][q] = 0.f;

#pragma unroll
            for (int kk = 0; kk < 2; kk++)
#pragma unroll
                for (int mt = 0; mt < 2; mt++)
#pragma unroll
                    for (int nt = 0; nt < 2; nt++)
                        MMA(acc[mt][nt], ah[mt][kk], bh[kk][nt][0], bh[kk][nt][1]);
#pragma unroll
            for (int mt = 0; mt < 2; mt++)
#pragma unroll
                for (int nt = 0; nt < 2; nt++)
                    MMA(acc[mt][nt], aga[mt], bga[nt][0], bga[nt][1]);

            // epilogue: acc IS the full exp2 argument
#pragma unroll
            for (int mt = 0; mt < 2; mt++)
#pragma unroll
                for (int nt = 0; nt < 2; nt++) {
                    float e0, e1, e2, e3;
                    asm("ex2.approx.f32 %0, %1;" : "=f"(e0) : "f"(acc[mt][nt][0]));
                    asm("ex2.approx.f32 %0, %1;" : "=f"(e1) : "f"(acc[mt][nt][1]));
                    asm("ex2.approx.f32 %0, %1;" : "=f"(e2) : "f"(acc[mt][nt][2]));
                    asm("ex2.approx.f32 %0, %1;" : "=f"(e3) : "f"(acc[mt][nt][3]));
                    rs[mt * 2 + 0] += e0 + e1;
                    rs[mt * 2 + 1] += e2 + e3;
                }
        }
    }

    // deterministic reduction: 4 lanes share each row
#pragma unroll
    for (int k = 0; k < 4; k++) {
        rs[k] += __shfl_xor_sync(0xffffffffu, rs[k], 1);
        rs[k] += __shfl_xor_sync(0xffffffffu, rs[k], 2);
    }
    __syncthreads();
    float* red = (float*)(smem + SM_Y);  // 256 floats, buffers no longer needed
    if ((lane & 3) == 0) {
#pragma unroll
        for (int k = 0; k < 4; k++) {
            int mt = k >> 1, hf = k & 1;
            int row = wm * 32 + mt * 16 + (lane >> 2) + hf * 8;
            red[wn * 128 + row] = rs[k];
        }
    }
    __syncthreads();
    if (tid < 128)
        g_partial[split * Qn + qb + tid] = red[tid] + red[128 + tid];
}

__global__ void finalize(float* __restrict__ out) {
    int i = blockIdx.x * blockDim.x + threadIdx.x;
    if (i >= Qn) return;
    float s = 0.f;
#pragma unroll
    for (int k = 0; k < SPLITN; k++) s += g_partial[k * Qn + i];
    out[i] = logf(s) - 29.40603306f - g_logsumw;
}

// ---------------------------------------------------------------------------
extern "C" void kernel_launch(void* const* d_in, const int* in_sizes, int n_in,
                              void* d_out, int out_size) {
    const float* X = (const float*)d_in[0];  // [4096,32]
    const float* Y = (const float*)d_in[1];  // [65536,32]
    const float* W = (const float*)d_in[2];  // [65536]
    float* out = (float*)d_out;

    cudaFuncSetAttribute(kde_main, cudaFuncAttributeMaxDynamicSharedMemorySize, SM_BYTES);

    prep_x48<<<(Qn + 255) / 256, 256>>>(X);
    prep_y48<<<Nn / 256, 256>>>(Y, W);
    sumw2<<<1, 256>>>();
    dim3 grid(Qn / BM, SPLITN);
    kde_main<<<grid, 256, SM_BYTES>>>();
    finalize<<<(Qn + 255) / 256, 256>>>(out);
}